// round 4
// baseline (speedup 1.0000x reference)
#include <cuda_runtime.h>
#include <cuda_bf16.h>
#include <math.h>

#define N_NODES 100000
#define E_MAX   1600000
#define ET_MAX  (E_MAX + N_NODES)
#define HID     64
#define IN_DIM  128
#define NCLS    40
#define SCAN_CHUNK 1024

// ---------------- scratch (device globals; no allocation allowed) ----------
__device__ float g_h[(size_t)N_NODES * HID];
__device__ float g_acc[(size_t)N_NODES * HID];
__device__ float g_s[N_NODES];
__device__ float g_d[N_NODES];
__device__ int   g_deg[N_NODES];
__device__ int   g_tmp[N_NODES];
__device__ int   g_rowptr[N_NODES];
__device__ int   g_cursor[N_NODES];
__device__ int   g_bsum[128];
__device__ int   g_csr[ET_MAX];
__device__ int2  g_epack[ET_MAX];               // decoded (src,dst)
__device__ int   g_is64;

// ---------------- helpers ---------------------------------------------------
__device__ __forceinline__ void load_edge(const void* ei, int i, int E,
                                          int& src, int& dst) {
    if (i >= E) { int v = i - E; src = v; dst = v; return; }   // self-loop
    if (g_is64) {
        const long long* p = (const long long*)ei;
        src = (int)p[i];
        dst = (int)p[(long long)E + i];
    } else {
        const int* p = (const int*)ei;
        src = p[i];
        dst = p[E + i];
    }
}

__device__ __forceinline__ unsigned bfpack(float x, float y) {
    __nv_bfloat162 h = __floats2bfloat162_rn(x, y);
    return *reinterpret_cast<unsigned*>(&h);
}

__device__ __forceinline__ void mma16816(float* c, const unsigned* a,
                                         const unsigned* b) {
    asm volatile(
        "mma.sync.aligned.m16n8k16.row.col.f32.bf16.bf16.f32 "
        "{%0,%1,%2,%3}, {%4,%5,%6,%7}, {%8,%9}, {%0,%1,%2,%3};"
        : "+f"(c[0]), "+f"(c[1]), "+f"(c[2]), "+f"(c[3])
        : "r"(a[0]), "r"(a[1]), "r"(a[2]), "r"(a[3]), "r"(b[0]), "r"(b[1]));
}

// ---------------- CSR build --------------------------------------------------
__global__ void zero_detect_kernel(const void* ei, int n) {
    int i = blockIdx.x * blockDim.x + threadIdx.x;
    if (i < n) g_deg[i] = 0;
    if (i == 0) {
        const int* p = (const int*)ei;
        int is64 = 1;
        for (int k = 0; k < 1024; k++)
            if (p[2 * k + 1] != 0) { is64 = 0; break; }
        g_is64 = is64;
    }
}

__global__ void hist_kernel(const void* ei, int E, int ET) {
    int i = blockIdx.x * blockDim.x + threadIdx.x;
    if (i >= ET) return;
    int src, dst;
    load_edge(ei, i, E, src, dst);
    g_epack[i] = make_int2(src, dst);
    atomicAdd(&g_deg[dst], 1);
}

__global__ void scan1_kernel(int n) {          // inclusive scan per 1024-chunk
    __shared__ int s[SCAN_CHUNK];
    int i = blockIdx.x * SCAN_CHUNK + threadIdx.x;
    int v = (i < n) ? g_deg[i] : 0;
    s[threadIdx.x] = v;
    __syncthreads();
#pragma unroll
    for (int off = 1; off < SCAN_CHUNK; off <<= 1) {
        int t = (threadIdx.x >= off) ? s[threadIdx.x - off] : 0;
        __syncthreads();
        s[threadIdx.x] += t;
        __syncthreads();
    }
    if (i < n) g_tmp[i] = s[threadIdx.x];
    if (threadIdx.x == SCAN_CHUNK - 1) g_bsum[blockIdx.x] = s[SCAN_CHUNK - 1];
}

__global__ void scan2_kernel(int nb) {
    __shared__ int s[128];
    int v = (threadIdx.x < nb) ? g_bsum[threadIdx.x] : 0;
    s[threadIdx.x] = v;
    __syncthreads();
#pragma unroll
    for (int off = 1; off < 128; off <<= 1) {
        int t = (threadIdx.x >= off) ? s[threadIdx.x - off] : 0;
        __syncthreads();
        s[threadIdx.x] += t;
        __syncthreads();
    }
    if (threadIdx.x < nb) g_bsum[threadIdx.x] = s[threadIdx.x] - v;
}

__global__ void scan3_kernel(int n) {
    int i = blockIdx.x * SCAN_CHUNK + threadIdx.x;
    if (i >= n) return;
    int start = g_tmp[i] - g_deg[i] + g_bsum[blockIdx.x];
    g_rowptr[i] = start;
    g_cursor[i] = start;
}

__global__ void fill_kernel(int ET) {
    int i = blockIdx.x * blockDim.x + threadIdx.x;
    if (i >= ET) return;
    int2 e = g_epack[i];
    int pos = atomicAdd(&g_cursor[e.y], 1);
    g_csr[pos] = e.x;
}

// ---------------- tensor-core GEMM (bf16x3 split) + fused s/d ---------------
// O[n,64] = A[n,K] @ W[K,64];  s[v] = O[v]·a_s;  d[v] = O[v]·a_d
// block: 64 rows x 64 cols, 256 thr (8 warps: 4 M x 2 N), warp: 16x32.
template <int K>
__global__ void gemm_mma_kernel(const float* __restrict__ A,
                                const float* __restrict__ W,
                                const float* __restrict__ a_s,
                                const float* __restrict__ a_d,
                                float* __restrict__ O, int n) {
    __shared__ float xs[64][33];
    __shared__ float ws[32][65];
    __shared__ float sas[64], sad[64];
    __shared__ float s_red[2][64], d_red[2][64];

    int tid  = threadIdx.x;
    int warp = tid >> 5, lane = tid & 31;
    int wm = warp >> 1, wn = warp & 1;
    int g = lane >> 2, t = lane & 3;
    int row0 = blockIdx.x * 64;

    if (tid < 64) { sas[tid] = a_s[tid]; sad[tid] = a_d[tid]; }

    float c[4][4] = {};

    for (int k0 = 0; k0 < K; k0 += 32) {
#pragma unroll
        for (int i = 0; i < 2; i++) {               // A tile 64x32 fp32
            int idx = i * 256 + tid;                // float4 granule
            int r = idx >> 3, c4 = idx & 7;
            float4 v = make_float4(0.f, 0.f, 0.f, 0.f);
            int gr = row0 + r;
            if (gr < n) v = *(const float4*)&A[(size_t)gr * K + k0 + c4 * 4];
            xs[r][c4 * 4 + 0] = v.x; xs[r][c4 * 4 + 1] = v.y;
            xs[r][c4 * 4 + 2] = v.z; xs[r][c4 * 4 + 3] = v.w;
        }
#pragma unroll
        for (int i = 0; i < 2; i++) {               // W tile 32x64 fp32
            int idx = i * 256 + tid;
            int r = idx >> 4, c4 = idx & 15;
            float4 v = *(const float4*)&W[(size_t)(k0 + r) * 64 + c4 * 4];
            ws[r][c4 * 4 + 0] = v.x; ws[r][c4 * 4 + 1] = v.y;
            ws[r][c4 * 4 + 2] = v.z; ws[r][c4 * 4 + 3] = v.w;
        }
        __syncthreads();

#pragma unroll
        for (int kk = 0; kk < 32; kk += 16) {
            // ---- A fragments (rows wm*16+g, +8; k cols kk+2t(+1), +8(+9))
            int r0 = wm * 16 + g, r1 = r0 + 8, kc = kk + 2 * t;
            unsigned a_hi[4], a_lo[4];
#pragma unroll
            for (int p = 0; p < 4; p++) {
                int rr = (p & 1) ? r1 : r0;
                int cc = kc + ((p >> 1) ? 8 : 0);
                float x = xs[rr][cc], y = xs[rr][cc + 1];
                __nv_bfloat162 h2 = __floats2bfloat162_rn(x, y);
                float2 hf = __bfloat1622float2(h2);
                a_hi[p] = *reinterpret_cast<unsigned*>(&h2);
                a_lo[p] = bfpack(x - hf.x, y - hf.y);
            }
            // ---- B fragments + 3-term MMA, 4 n8 frags
#pragma unroll
            for (int f = 0; f < 4; f++) {
                int col = wn * 32 + f * 8 + g;
                unsigned b_hi[2], b_lo[2];
#pragma unroll
                for (int p = 0; p < 2; p++) {
                    int krow = kk + 2 * t + (p ? 8 : 0);
                    float x = ws[krow][col], y = ws[krow + 1][col];
                    __nv_bfloat162 h2 = __floats2bfloat162_rn(x, y);
                    float2 hf = __bfloat1622float2(h2);
                    b_hi[p] = *reinterpret_cast<unsigned*>(&h2);
                    b_lo[p] = bfpack(x - hf.x, y - hf.y);
                }
                mma16816(c[f], a_hi, b_hi);
                mma16816(c[f], a_hi, b_lo);
                mma16816(c[f], a_lo, b_hi);
            }
        }
        __syncthreads();
    }

    // ---- epilogue: store O + fused s/d
    int r0 = wm * 16 + g, r1 = r0 + 8;
    int gr0 = row0 + r0, gr1 = row0 + r1;
    float s0 = 0.f, s1 = 0.f, d0 = 0.f, d1 = 0.f;
#pragma unroll
    for (int f = 0; f < 4; f++) {
        int col = wn * 32 + f * 8 + 2 * t;
        if (gr0 < n) *(float2*)&O[(size_t)gr0 * 64 + col] = make_float2(c[f][0], c[f][1]);
        if (gr1 < n) *(float2*)&O[(size_t)gr1 * 64 + col] = make_float2(c[f][2], c[f][3]);
        float as0 = sas[col], as1 = sas[col + 1];
        float ad0 = sad[col], ad1 = sad[col + 1];
        s0 += c[f][0] * as0 + c[f][1] * as1;
        s1 += c[f][2] * as0 + c[f][3] * as1;
        d0 += c[f][0] * ad0 + c[f][1] * ad1;
        d1 += c[f][2] * ad0 + c[f][3] * ad1;
    }
#pragma unroll
    for (int off = 1; off < 4; off <<= 1) {        // reduce over t (4-lane group)
        s0 += __shfl_xor_sync(0xffffffffu, s0, off);
        s1 += __shfl_xor_sync(0xffffffffu, s1, off);
        d0 += __shfl_xor_sync(0xffffffffu, d0, off);
        d1 += __shfl_xor_sync(0xffffffffu, d1, off);
    }
    if (t == 0) {
        s_red[wn][r0] = s0; s_red[wn][r1] = s1;
        d_red[wn][r0] = d0; d_red[wn][r1] = d1;
    }
    __syncthreads();
    if (tid < 64 && row0 + tid < n) {
        g_s[row0 + tid] = s_red[0][tid] + s_red[1][tid];
        g_d[row0 + tid] = d_red[0][tid] + d_red[1][tid];
    }
}

// ---------------- fused softmax + aggregation + bias + ELU ------------------
__device__ __forceinline__ float att_p(int src, float dv) {
    float ev = g_s[src] + dv;
    ev = ev > 0.f ? ev : 0.2f * ev;                // leaky_relu(0.2)
    return __expf(ev);
}

__global__ void agg_kernel(const float* __restrict__ h,
                           const float* __restrict__ bias,
                           float* __restrict__ out, int n) {
    int v = (blockIdx.x * blockDim.x + threadIdx.x) >> 4;
    int l = threadIdx.x & 15;
    if (v >= n) return;
    int e0 = g_rowptr[v], e1 = g_cursor[v];
    float dv = g_d[v];
    float4 acc = make_float4(0.f, 0.f, 0.f, 0.f);
    float den = 0.f;
    int e = e0;
    for (; e + 1 < e1; e += 2) {
        int s0 = g_csr[e], s1 = g_csr[e + 1];
        float p0 = att_p(s0, dv);
        float p1 = att_p(s1, dv);
        float4 h0 = *(const float4*)&h[(size_t)s0 * HID + l * 4];
        float4 h1 = *(const float4*)&h[(size_t)s1 * HID + l * 4];
        den += p0 + p1;
        acc.x += p0 * h0.x + p1 * h1.x;
        acc.y += p0 * h0.y + p1 * h1.y;
        acc.z += p0 * h0.z + p1 * h1.z;
        acc.w += p0 * h0.w + p1 * h1.w;
    }
    if (e < e1) {
        int s0 = g_csr[e];
        float p0 = att_p(s0, dv);
        float4 h0 = *(const float4*)&h[(size_t)s0 * HID + l * 4];
        den += p0;
        acc.x += p0 * h0.x; acc.y += p0 * h0.y;
        acc.z += p0 * h0.z; acc.w += p0 * h0.w;
    }
    float inv = 1.f / (den + 1e-16f);
    float4 b4 = *(const float4*)&bias[l * 4];
    float4 o;
    o.x = acc.x * inv + b4.x;
    o.y = acc.y * inv + b4.y;
    o.z = acc.z * inv + b4.z;
    o.w = acc.w * inv + b4.w;
    o.x = o.x > 0.f ? o.x : expm1f(o.x);
    o.y = o.y > 0.f ? o.y : expm1f(o.y);
    o.z = o.z > 0.f ? o.z : expm1f(o.z);
    o.w = o.w > 0.f ? o.w : expm1f(o.w);
    *(float4*)&out[(size_t)v * HID + l * 4] = o;
}

// ---------------- head: out[n,40] = h[n,64] @ Wl + bl -----------------------
__global__ void logits_kernel(const float* __restrict__ h,
                              const float* __restrict__ Wl,
                              const float* __restrict__ bl,
                              float* __restrict__ out, int n) {
    __shared__ float hs[64][65];
    __shared__ float ws[HID * NCLS];
    __shared__ float bs[NCLS];
    int tid = threadIdx.x;
    int rg = tid / 10;            // 0..15
    int cg = tid % 10;            // 0..9
    int row0 = blockIdx.x * 64;
    for (int idx = tid; idx < 64 * 16; idx += 160) {
        int r = idx >> 4, c4 = idx & 15;
        float4 v = make_float4(0.f, 0.f, 0.f, 0.f);
        int gr = row0 + r;
        if (gr < n) v = *(const float4*)&h[(size_t)gr * HID + c4 * 4];
        hs[r][c4 * 4 + 0] = v.x; hs[r][c4 * 4 + 1] = v.y;
        hs[r][c4 * 4 + 2] = v.z; hs[r][c4 * 4 + 3] = v.w;
    }
    for (int i = tid; i < HID * NCLS; i += 160) ws[i] = Wl[i];
    if (tid < NCLS) bs[tid] = bl[tid];
    __syncthreads();
    float acc[4][4];
#pragma unroll
    for (int r = 0; r < 4; r++)
#pragma unroll
        for (int c = 0; c < 4; c++) acc[r][c] = bs[cg * 4 + c];
#pragma unroll 8
    for (int k = 0; k < HID; k++) {
        float xv[4];
#pragma unroll
        for (int r = 0; r < 4; r++) xv[r] = hs[rg * 4 + r][k];
        float4 w = *(float4*)&ws[k * NCLS + cg * 4];
#pragma unroll
        for (int r = 0; r < 4; r++) {
            acc[r][0] += xv[r] * w.x; acc[r][1] += xv[r] * w.y;
            acc[r][2] += xv[r] * w.z; acc[r][3] += xv[r] * w.w;
        }
    }
#pragma unroll
    for (int r = 0; r < 4; r++) {
        int gr = row0 + rg * 4 + r;
        if (gr < n)
            *(float4*)&out[(size_t)gr * NCLS + cg * 4] =
                make_float4(acc[r][0], acc[r][1], acc[r][2], acc[r][3]);
    }
}

// ---------------- launcher --------------------------------------------------
extern "C" void kernel_launch(void* const* d_in, const int* in_sizes, int n_in,
                              void* d_out, int out_size) {
    const float* x    = (const float*)d_in[0];
    const void*  ei   = d_in[1];
    const float* W0   = (const float*)d_in[2];
    const float* a_s0 = (const float*)d_in[3];
    const float* a_d0 = (const float*)d_in[4];
    const float* b0   = (const float*)d_in[5];
    const float* W1   = (const float*)d_in[6];
    const float* a_s1 = (const float*)d_in[7];
    const float* a_d1 = (const float*)d_in[8];
    const float* b1   = (const float*)d_in[9];
    const float* Wl   = (const float*)d_in[10];
    const float* bl   = (const float*)d_in[11];
    float* out = (float*)d_out;

    int n  = in_sizes[0] / IN_DIM;   // 100000
    int E  = in_sizes[1] / 2;        // 1600000
    int ET = E + n;

    float* hbuf;  cudaGetSymbolAddress((void**)&hbuf, g_h);
    float* abuf;  cudaGetSymbolAddress((void**)&abuf, g_acc);

    int scanBlocks = (n + SCAN_CHUNK - 1) / SCAN_CHUNK;   // 98
    int edgeBlocks = (ET + 255) / 256;
    int nodeBlocks = (n + 255) / 256;
    int hwBlocks   = (n + 15) / 16;

    // ---- CSR build (shared by both layers) ----
    zero_detect_kernel<<<nodeBlocks, 256>>>(ei, n);
    hist_kernel<<<edgeBlocks, 256>>>(ei, E, ET);
    scan1_kernel<<<scanBlocks, SCAN_CHUNK>>>(n);
    scan2_kernel<<<1, 128>>>(scanBlocks);
    scan3_kernel<<<scanBlocks, SCAN_CHUNK>>>(n);
    fill_kernel<<<edgeBlocks, 256>>>(ET);

    // ---- layer 0 ----
    gemm_mma_kernel<IN_DIM><<<(n + 63) / 64, 256>>>(x, W0, a_s0, a_d0, hbuf, n);
    agg_kernel<<<hwBlocks, 256>>>(hbuf, b0, abuf, n);

    // ---- layer 1 ----
    gemm_mma_kernel<HID><<<(n + 63) / 64, 256>>>(abuf, W1, a_s1, a_d1, hbuf, n);
    agg_kernel<<<hwBlocks, 256>>>(hbuf, b1, abuf, n);

    // ---- head ----
    logits_kernel<<<(n + 63) / 64, 160>>>(abuf, Wl, bl, out, n);
}

// round 5
// speedup vs baseline: 1.1101x; 1.1101x over previous
#include <cuda_runtime.h>
#include <cuda_fp16.h>
#include <math.h>

#define N_NODES 100000
#define E_MAX   1600000
#define ET_MAX  (E_MAX + N_NODES)
#define HID     64
#define IN_DIM  128
#define NCLS    40
#define SCAN_CHUNK 1024

// ---------------- scratch (device globals; no allocation allowed) ----------
__device__ __half g_h[(size_t)N_NODES * HID];   // transformed features (fp16)
__device__ float  g_acc[(size_t)N_NODES * HID]; // layer output / next input
__device__ float  g_s[N_NODES];
__device__ float  g_d[N_NODES];
__device__ int    g_deg[N_NODES];
__device__ int    g_tmp[N_NODES];
__device__ int    g_rowptr[N_NODES];
__device__ int    g_cursor[N_NODES];
__device__ int    g_bsum[128];
__device__ int    g_csr[ET_MAX];
__device__ int2   g_epack[ET_MAX];
__device__ int    g_is64;

// ---------------- helpers ---------------------------------------------------
__device__ __forceinline__ void load_edge(const void* ei, int i, int E,
                                          int& src, int& dst) {
    if (i >= E) { int v = i - E; src = v; dst = v; return; }   // self-loop
    if (g_is64) {
        const long long* p = (const long long*)ei;
        src = (int)p[i];
        dst = (int)p[(long long)E + i];
    } else {
        const int* p = (const int*)ei;
        src = p[i];
        dst = p[E + i];
    }
}

// ---------------- CSR build --------------------------------------------------
__global__ void zero_detect_kernel(const void* ei, int n) {
    int i = blockIdx.x * blockDim.x + threadIdx.x;
    if (i < n) g_deg[i] = 0;
    if (i == 0) {
        const int* p = (const int*)ei;
        int is64 = 1;
        for (int k = 0; k < 1024; k++)
            if (p[2 * k + 1] != 0) { is64 = 0; break; }
        g_is64 = is64;
    }
}

__global__ void hist_kernel(const void* ei, int E, int ET) {
    int i = blockIdx.x * blockDim.x + threadIdx.x;
    if (i >= ET) return;
    int src, dst;
    load_edge(ei, i, E, src, dst);
    g_epack[i] = make_int2(src, dst);
    atomicAdd(&g_deg[dst], 1);
}

__global__ void scan1_kernel(int n) {          // inclusive scan per 1024-chunk
    __shared__ int s[SCAN_CHUNK];
    int i = blockIdx.x * SCAN_CHUNK + threadIdx.x;
    int v = (i < n) ? g_deg[i] : 0;
    s[threadIdx.x] = v;
    __syncthreads();
#pragma unroll
    for (int off = 1; off < SCAN_CHUNK; off <<= 1) {
        int t = (threadIdx.x >= off) ? s[threadIdx.x - off] : 0;
        __syncthreads();
        s[threadIdx.x] += t;
        __syncthreads();
    }
    if (i < n) g_tmp[i] = s[threadIdx.x];
    if (threadIdx.x == SCAN_CHUNK - 1) g_bsum[blockIdx.x] = s[SCAN_CHUNK - 1];
}

__global__ void scan2_kernel(int nb) {
    __shared__ int s[128];
    int v = (threadIdx.x < nb) ? g_bsum[threadIdx.x] : 0;
    s[threadIdx.x] = v;
    __syncthreads();
#pragma unroll
    for (int off = 1; off < 128; off <<= 1) {
        int t = (threadIdx.x >= off) ? s[threadIdx.x - off] : 0;
        __syncthreads();
        s[threadIdx.x] += t;
        __syncthreads();
    }
    if (threadIdx.x < nb) g_bsum[threadIdx.x] = s[threadIdx.x] - v;
}

__global__ void scan3_kernel(int n) {
    int i = blockIdx.x * SCAN_CHUNK + threadIdx.x;
    if (i >= n) return;
    int start = g_tmp[i] - g_deg[i] + g_bsum[blockIdx.x];
    g_rowptr[i] = start;
    g_cursor[i] = start;
}

__global__ void fill_kernel(int ET) {
    int i = blockIdx.x * blockDim.x + threadIdx.x;
    if (i >= ET) return;
    int2 e = g_epack[i];
    int pos = atomicAdd(&g_cursor[e.y], 1);
    g_csr[pos] = e.x;
}

// ---------------- dense transform + fused attention scalars -----------------
// O(fp16)[n,64] = A[n,K] @ W[K,64];  s[v]=O[v]·a_s;  d[v]=O[v]·a_d (fp32 acc)
// tile 64 rows x 64 cols, TK=32, 256 threads, 4x4 register block.
template <int K>
__global__ void gemm64_kernel(const float* __restrict__ A,
                              const float* __restrict__ W,
                              const float* __restrict__ a_s,
                              const float* __restrict__ a_d,
                              __half* __restrict__ O, int n) {
    __shared__ float xs[64][33];
    __shared__ float ws[32][64];
    int tid = threadIdx.x;
    int rg = tid >> 4;            // 0..15 -> rows rg*4..+3
    int cg = tid & 15;            // 0..15 -> cols cg*4..+3
    int row0 = blockIdx.x * 64;
    float4 asv = *(const float4*)&a_s[cg * 4];
    float4 adv = *(const float4*)&a_d[cg * 4];
    float acc[4][4] = {};
    for (int k0 = 0; k0 < K; k0 += 32) {
#pragma unroll
        for (int i = 0; i < 2; i++) {
            int idx = i * 256 + tid;      // float4 index into 64x32 x-tile
            int r = idx >> 3, c4 = idx & 7;
            float4 v = make_float4(0.f, 0.f, 0.f, 0.f);
            int gr = row0 + r;
            if (gr < n) v = *(const float4*)&A[(size_t)gr * K + k0 + c4 * 4];
            xs[r][c4 * 4 + 0] = v.x; xs[r][c4 * 4 + 1] = v.y;
            xs[r][c4 * 4 + 2] = v.z; xs[r][c4 * 4 + 3] = v.w;
        }
#pragma unroll
        for (int i = 0; i < 2; i++) {
            int idx = i * 256 + tid;      // float4 index into 32x64 w-tile
            int r = idx >> 4, c4 = idx & 15;
            *(float4*)&ws[r][c4 * 4] = *(const float4*)&W[(size_t)(k0 + r) * 64 + c4 * 4];
        }
        __syncthreads();
#pragma unroll
        for (int kk = 0; kk < 32; kk++) {
            float xv[4];
#pragma unroll
            for (int r = 0; r < 4; r++) xv[r] = xs[rg * 4 + r][kk];
            float4 w = *(float4*)&ws[kk][cg * 4];
#pragma unroll
            for (int r = 0; r < 4; r++) {
                acc[r][0] += xv[r] * w.x; acc[r][1] += xv[r] * w.y;
                acc[r][2] += xv[r] * w.z; acc[r][3] += xv[r] * w.w;
            }
        }
        __syncthreads();
    }
#pragma unroll
    for (int r = 0; r < 4; r++) {
        int gr = row0 + rg * 4 + r;
        if (gr < n) {
            __half2 h01 = __floats2half2_rn(acc[r][0], acc[r][1]);
            __half2 h23 = __floats2half2_rn(acc[r][2], acc[r][3]);
            uint2 pk;
            pk.x = *reinterpret_cast<unsigned*>(&h01);
            pk.y = *reinterpret_cast<unsigned*>(&h23);
            *(uint2*)&O[(size_t)gr * 64 + cg * 4] = pk;
        }
        // fused s/d: reduce across the 16 threads (one half-warp) sharing rg
        float sv = acc[r][0] * asv.x + acc[r][1] * asv.y +
                   acc[r][2] * asv.z + acc[r][3] * asv.w;
        float dv = acc[r][0] * adv.x + acc[r][1] * adv.y +
                   acc[r][2] * adv.z + acc[r][3] * adv.w;
#pragma unroll
        for (int off = 8; off; off >>= 1) {
            sv += __shfl_down_sync(0xffffffffu, sv, off, 16);
            dv += __shfl_down_sync(0xffffffffu, dv, off, 16);
        }
        if (cg == 0 && gr < n) { g_s[gr] = sv; g_d[gr] = dv; }
    }
}

// ---------------- fused softmax + aggregation + bias + ELU ------------------
// 8 lanes per dst node; lane handles 8 channels (one uint4 = 8 halves/edge).
__device__ __forceinline__ float att_p(int src, float dv) {
    float ev = g_s[src] + dv;
    ev = ev > 0.f ? ev : 0.2f * ev;                // leaky_relu(0.2)
    return __expf(ev);                              // logits bounded; no max-shift
}

__device__ __forceinline__ void acc_edge(float* acc, float p, uint4 u) {
    const __half2* h2 = reinterpret_cast<const __half2*>(&u);
#pragma unroll
    for (int i = 0; i < 4; i++) {
        float2 f = __half22float2(h2[i]);
        acc[2 * i]     += p * f.x;
        acc[2 * i + 1] += p * f.y;
    }
}

__global__ void agg_kernel(const __half* __restrict__ h,
                           const float* __restrict__ bias,
                           float* __restrict__ out, int n) {
    int v = (blockIdx.x * blockDim.x + threadIdx.x) >> 3;
    int l = threadIdx.x & 7;
    if (v >= n) return;
    int e0 = g_rowptr[v], e1 = g_cursor[v];
    float dv = g_d[v];
    float acc[8] = {};
    float den = 0.f;
    int e = e0;
    for (; e + 1 < e1; e += 2) {                    // 2-edge unroll for MLP
        int s0 = g_csr[e], s1 = g_csr[e + 1];
        float p0 = att_p(s0, dv);
        float p1 = att_p(s1, dv);
        uint4 u0 = *(const uint4*)&h[(size_t)s0 * HID + l * 8];
        uint4 u1 = *(const uint4*)&h[(size_t)s1 * HID + l * 8];
        den += p0 + p1;
        acc_edge(acc, p0, u0);
        acc_edge(acc, p1, u1);
    }
    if (e < e1) {
        int s0 = g_csr[e];
        float p0 = att_p(s0, dv);
        uint4 u0 = *(const uint4*)&h[(size_t)s0 * HID + l * 8];
        den += p0;
        acc_edge(acc, p0, u0);
    }
    float inv = 1.f / (den + 1e-16f);
    float4 b0 = *(const float4*)&bias[l * 8];
    float4 b1 = *(const float4*)&bias[l * 8 + 4];
    float o[8];
#pragma unroll
    for (int i = 0; i < 8; i++) {
        float bv = (i < 4) ? ((const float*)&b0)[i] : ((const float*)&b1)[i - 4];
        float x = acc[i] * inv + bv;
        o[i] = x > 0.f ? x : expm1f(x);             // ELU
    }
    *(float4*)&out[(size_t)v * HID + l * 8]     = make_float4(o[0], o[1], o[2], o[3]);
    *(float4*)&out[(size_t)v * HID + l * 8 + 4] = make_float4(o[4], o[5], o[6], o[7]);
}

// ---------------- head: out[n,40] = h[n,64] @ Wl + bl -----------------------
__global__ void logits_kernel(const float* __restrict__ h,
                              const float* __restrict__ Wl,
                              const float* __restrict__ bl,
                              float* __restrict__ out, int n) {
    __shared__ float hs[64][65];
    __shared__ float ws[HID * NCLS];
    __shared__ float bs[NCLS];
    int tid = threadIdx.x;
    int rg = tid / 10;            // 0..15
    int cg = tid % 10;            // 0..9
    int row0 = blockIdx.x * 64;
    for (int idx = tid; idx < 64 * 16; idx += 160) {
        int r = idx >> 4, c4 = idx & 15;
        float4 v = make_float4(0.f, 0.f, 0.f, 0.f);
        int gr = row0 + r;
        if (gr < n) v = *(const float4*)&h[(size_t)gr * HID + c4 * 4];
        hs[r][c4 * 4 + 0] = v.x; hs[r][c4 * 4 + 1] = v.y;
        hs[r][c4 * 4 + 2] = v.z; hs[r][c4 * 4 + 3] = v.w;
    }
    for (int i = tid; i < HID * NCLS; i += 160) ws[i] = Wl[i];
    if (tid < NCLS) bs[tid] = bl[tid];
    __syncthreads();
    float acc[4][4];
#pragma unroll
    for (int r = 0; r < 4; r++)
#pragma unroll
        for (int c = 0; c < 4; c++) acc[r][c] = bs[cg * 4 + c];
#pragma unroll 8
    for (int k = 0; k < HID; k++) {
        float xv[4];
#pragma unroll
        for (int r = 0; r < 4; r++) xv[r] = hs[rg * 4 + r][k];
        float4 w = *(float4*)&ws[k * NCLS + cg * 4];
#pragma unroll
        for (int r = 0; r < 4; r++) {
            acc[r][0] += xv[r] * w.x; acc[r][1] += xv[r] * w.y;
            acc[r][2] += xv[r] * w.z; acc[r][3] += xv[r] * w.w;
        }
    }
#pragma unroll
    for (int r = 0; r < 4; r++) {
        int gr = row0 + rg * 4 + r;
        if (gr < n)
            *(float4*)&out[(size_t)gr * NCLS + cg * 4] =
                make_float4(acc[r][0], acc[r][1], acc[r][2], acc[r][3]);
    }
}

// ---------------- launcher --------------------------------------------------
extern "C" void kernel_launch(void* const* d_in, const int* in_sizes, int n_in,
                              void* d_out, int out_size) {
    const float* x    = (const float*)d_in[0];
    const void*  ei   = d_in[1];
    const float* W0   = (const float*)d_in[2];
    const float* a_s0 = (const float*)d_in[3];
    const float* a_d0 = (const float*)d_in[4];
    const float* b0   = (const float*)d_in[5];
    const float* W1   = (const float*)d_in[6];
    const float* a_s1 = (const float*)d_in[7];
    const float* a_d1 = (const float*)d_in[8];
    const float* b1   = (const float*)d_in[9];
    const float* Wl   = (const float*)d_in[10];
    const float* bl   = (const float*)d_in[11];
    float* out = (float*)d_out;

    int n  = in_sizes[0] / IN_DIM;   // 100000
    int E  = in_sizes[1] / 2;        // 1600000
    int ET = E + n;

    __half* hbuf;  cudaGetSymbolAddress((void**)&hbuf, g_h);
    float*  abuf;  cudaGetSymbolAddress((void**)&abuf, g_acc);

    int scanBlocks = (n + SCAN_CHUNK - 1) / SCAN_CHUNK;   // 98
    int edgeBlocks = (ET + 255) / 256;
    int nodeBlocks = (n + 255) / 256;
    int aggBlocks  = ((size_t)n * 8 + 255) / 256;

    // ---- CSR build (shared by both layers) ----
    zero_detect_kernel<<<nodeBlocks, 256>>>(ei, n);
    hist_kernel<<<edgeBlocks, 256>>>(ei, E, ET);
    scan1_kernel<<<scanBlocks, SCAN_CHUNK>>>(n);
    scan2_kernel<<<1, 128>>>(scanBlocks);
    scan3_kernel<<<scanBlocks, SCAN_CHUNK>>>(n);
    fill_kernel<<<edgeBlocks, 256>>>(ET);

    // ---- layer 0 ----
    gemm64_kernel<IN_DIM><<<(n + 63) / 64, 256>>>(x, W0, a_s0, a_d0, hbuf, n);
    agg_kernel<<<aggBlocks, 256>>>(hbuf, b0, abuf, n);

    // ---- layer 1 ----
    gemm64_kernel<HID><<<(n + 63) / 64, 256>>>(abuf, W1, a_s1, a_d1, hbuf, n);
    agg_kernel<<<aggBlocks, 256>>>(hbuf, b1, abuf, n);

    // ---- head ----
    logits_kernel<<<(n + 63) / 64, 160>>>(abuf, Wl, bl, out, n);
}

// round 6
// speedup vs baseline: 1.1586x; 1.0436x over previous
#include <cuda_runtime.h>
#include <cuda_fp16.h>
#include <math.h>

#define N_NODES 100000
#define E_MAX   1600000
#define ET_MAX  (E_MAX + N_NODES)
#define HID     64
#define IN_DIM  128
#define NCLS    40
#define SCAN_CHUNK 1024

// ---------------- scratch (device globals; no allocation allowed) ----------
__device__ __half g_h[(size_t)N_NODES * HID];   // transformed features (fp16)
__device__ float  g_acc[(size_t)N_NODES * HID]; // layer output / next input
__device__ float  g_s[N_NODES];
__device__ float  g_d[N_NODES];
__device__ int    g_deg[N_NODES];
__device__ int    g_tmp[N_NODES];
__device__ int    g_rowptr[N_NODES];
__device__ int    g_cursor[N_NODES];
__device__ int    g_bsum[128];
__device__ int    g_csr[ET_MAX];
__device__ int2   g_epack[ET_MAX];
__device__ int    g_is64;

// ---------------- helpers ---------------------------------------------------
__device__ __forceinline__ void load_edge(const void* ei, int i, int E,
                                          int& src, int& dst) {
    if (i >= E) { int v = i - E; src = v; dst = v; return; }   // self-loop
    if (g_is64) {
        const long long* p = (const long long*)ei;
        src = (int)p[i];
        dst = (int)p[(long long)E + i];
    } else {
        const int* p = (const int*)ei;
        src = p[i];
        dst = p[E + i];
    }
}

// ---------------- CSR build --------------------------------------------------
__global__ void zero_detect_kernel(const void* ei, int n) {
    int i = blockIdx.x * blockDim.x + threadIdx.x;
    if (i < n) g_deg[i] = 0;
    if (i == 0) {
        const int* p = (const int*)ei;
        int is64 = 1;
        for (int k = 0; k < 1024; k++)
            if (p[2 * k + 1] != 0) { is64 = 0; break; }
        g_is64 = is64;
    }
}

__global__ void hist_kernel(const void* ei, int E, int ET) {
    int i = blockIdx.x * blockDim.x + threadIdx.x;
    if (i >= ET) return;
    int src, dst;
    load_edge(ei, i, E, src, dst);
    g_epack[i] = make_int2(src, dst);
    atomicAdd(&g_deg[dst], 1);
}

__global__ void scan1_kernel(int n) {          // inclusive scan per 1024-chunk
    __shared__ int s[SCAN_CHUNK];
    int i = blockIdx.x * SCAN_CHUNK + threadIdx.x;
    int v = (i < n) ? g_deg[i] : 0;
    s[threadIdx.x] = v;
    __syncthreads();
#pragma unroll
    for (int off = 1; off < SCAN_CHUNK; off <<= 1) {
        int t = (threadIdx.x >= off) ? s[threadIdx.x - off] : 0;
        __syncthreads();
        s[threadIdx.x] += t;
        __syncthreads();
    }
    if (i < n) g_tmp[i] = s[threadIdx.x];
    if (threadIdx.x == SCAN_CHUNK - 1) g_bsum[blockIdx.x] = s[SCAN_CHUNK - 1];
}

// scan3 with inlined block-sum prefix (one warp sums bsum[0..b-1])
__global__ void scan3_kernel(int n) {
    __shared__ int base_s;
    int b = blockIdx.x;
    if (threadIdx.x < 32) {
        int s = 0;
        for (int j = threadIdx.x; j < b; j += 32) s += g_bsum[j];
#pragma unroll
        for (int o = 16; o; o >>= 1) s += __shfl_xor_sync(0xffffffffu, s, o);
        if (threadIdx.x == 0) base_s = s;
    }
    __syncthreads();
    int i = b * SCAN_CHUNK + threadIdx.x;
    if (i >= n) return;
    int start = g_tmp[i] - g_deg[i] + base_s;
    g_rowptr[i] = start;
    g_cursor[i] = start;
}

__global__ void fill_kernel(int ET) {
    int i = blockIdx.x * blockDim.x + threadIdx.x;
    if (i >= ET) return;
    int2 e = g_epack[i];
    int pos = atomicAdd(&g_cursor[e.y], 1);
    g_csr[pos] = e.x;
}

// ---------------- dense transform + fused attention scalars -----------------
// O(fp16)[n,64] = A[n,K] @ W[K,64];  s[v]=O[v]·a_s;  d[v]=O[v]·a_d (fp32 acc)
template <int K>
__global__ void gemm64_kernel(const float* __restrict__ A,
                              const float* __restrict__ W,
                              const float* __restrict__ a_s,
                              const float* __restrict__ a_d,
                              __half* __restrict__ O, int n) {
    __shared__ float xs[64][33];
    __shared__ float ws[32][64];
    int tid = threadIdx.x;
    int rg = tid >> 4;            // 0..15 -> rows rg*4..+3
    int cg = tid & 15;            // 0..15 -> cols cg*4..+3
    int row0 = blockIdx.x * 64;
    float4 asv = *(const float4*)&a_s[cg * 4];
    float4 adv = *(const float4*)&a_d[cg * 4];
    float acc[4][4] = {};
    for (int k0 = 0; k0 < K; k0 += 32) {
#pragma unroll
        for (int i = 0; i < 2; i++) {
            int idx = i * 256 + tid;      // float4 index into 64x32 x-tile
            int r = idx >> 3, c4 = idx & 7;
            float4 v = make_float4(0.f, 0.f, 0.f, 0.f);
            int gr = row0 + r;
            if (gr < n) v = *(const float4*)&A[(size_t)gr * K + k0 + c4 * 4];
            xs[r][c4 * 4 + 0] = v.x; xs[r][c4 * 4 + 1] = v.y;
            xs[r][c4 * 4 + 2] = v.z; xs[r][c4 * 4 + 3] = v.w;
        }
#pragma unroll
        for (int i = 0; i < 2; i++) {
            int idx = i * 256 + tid;      // float4 index into 32x64 w-tile
            int r = idx >> 4, c4 = idx & 15;
            *(float4*)&ws[r][c4 * 4] = *(const float4*)&W[(size_t)(k0 + r) * 64 + c4 * 4];
        }
        __syncthreads();
#pragma unroll
        for (int kk = 0; kk < 32; kk++) {
            float xv[4];
#pragma unroll
            for (int r = 0; r < 4; r++) xv[r] = xs[rg * 4 + r][kk];
            float4 w = *(float4*)&ws[kk][cg * 4];
#pragma unroll
            for (int r = 0; r < 4; r++) {
                acc[r][0] += xv[r] * w.x; acc[r][1] += xv[r] * w.y;
                acc[r][2] += xv[r] * w.z; acc[r][3] += xv[r] * w.w;
            }
        }
        __syncthreads();
    }
#pragma unroll
    for (int r = 0; r < 4; r++) {
        int gr = row0 + rg * 4 + r;
        if (gr < n) {
            __half2 h01 = __floats2half2_rn(acc[r][0], acc[r][1]);
            __half2 h23 = __floats2half2_rn(acc[r][2], acc[r][3]);
            uint2 pk;
            pk.x = *reinterpret_cast<unsigned*>(&h01);
            pk.y = *reinterpret_cast<unsigned*>(&h23);
            *(uint2*)&O[(size_t)gr * 64 + cg * 4] = pk;
        }
        float sv = acc[r][0] * asv.x + acc[r][1] * asv.y +
                   acc[r][2] * asv.z + acc[r][3] * asv.w;
        float dv = acc[r][0] * adv.x + acc[r][1] * adv.y +
                   acc[r][2] * adv.z + acc[r][3] * adv.w;
#pragma unroll
        for (int off = 8; off; off >>= 1) {
            sv += __shfl_down_sync(0xffffffffu, sv, off, 16);
            dv += __shfl_down_sync(0xffffffffu, dv, off, 16);
        }
        if (cg == 0 && gr < n) { g_s[gr] = sv; g_d[gr] = dv; }
    }
}

// ---------------- fused softmax + aggregation + bias + ELU ------------------
__device__ __forceinline__ float att_p(int src, float dv) {
    float ev = g_s[src] + dv;
    ev = ev > 0.f ? ev : 0.2f * ev;                // leaky_relu(0.2)
    return __expf(ev);                              // logits bounded; no max-shift
}

__device__ __forceinline__ void acc_edge(float* acc, float p, uint4 u) {
    const __half2* h2 = reinterpret_cast<const __half2*>(&u);
#pragma unroll
    for (int i = 0; i < 4; i++) {
        float2 f = __half22float2(h2[i]);
        acc[2 * i]     += p * f.x;
        acc[2 * i + 1] += p * f.y;
    }
}

__global__ void agg_kernel(const __half* __restrict__ h,
                           const float* __restrict__ bias,
                           float* __restrict__ out, int n) {
    int v = (blockIdx.x * blockDim.x + threadIdx.x) >> 3;
    int l = threadIdx.x & 7;
    if (v >= n) return;
    int e0 = g_rowptr[v], e1 = g_cursor[v];
    float dv = g_d[v];
    float acc[8] = {};
    float den = 0.f;
    int e = e0;
    for (; e + 1 < e1; e += 2) {                    // 2-edge unroll for MLP
        int s0 = g_csr[e], s1 = g_csr[e + 1];
        float p0 = att_p(s0, dv);
        float p1 = att_p(s1, dv);
        uint4 u0 = *(const uint4*)&h[(size_t)s0 * HID + l * 8];
        uint4 u1 = *(const uint4*)&h[(size_t)s1 * HID + l * 8];
        den += p0 + p1;
        acc_edge(acc, p0, u0);
        acc_edge(acc, p1, u1);
    }
    if (e < e1) {
        int s0 = g_csr[e];
        float p0 = att_p(s0, dv);
        uint4 u0 = *(const uint4*)&h[(size_t)s0 * HID + l * 8];
        den += p0;
        acc_edge(acc, p0, u0);
    }
    float inv = 1.f / (den + 1e-16f);
    float4 b0 = *(const float4*)&bias[l * 8];
    float4 b1 = *(const float4*)&bias[l * 8 + 4];
    float o[8];
#pragma unroll
    for (int i = 0; i < 8; i++) {
        float bv = (i < 4) ? ((const float*)&b0)[i] : ((const float*)&b1)[i - 4];
        float x = acc[i] * inv + bv;
        o[i] = x > 0.f ? x : expm1f(x);             // ELU
    }
    *(float4*)&out[(size_t)v * HID + l * 8]     = make_float4(o[0], o[1], o[2], o[3]);
    *(float4*)&out[(size_t)v * HID + l * 8 + 4] = make_float4(o[4], o[5], o[6], o[7]);
}

// ---------------- head: out[n,40] = h[n,64] @ Wl + bl -----------------------
__global__ void logits_kernel(const float* __restrict__ h,
                              const float* __restrict__ Wl,
                              const float* __restrict__ bl,
                              float* __restrict__ out, int n) {
    __shared__ float hs[64][65];
    __shared__ float ws[HID * NCLS];
    __shared__ float bs[NCLS];
    int tid = threadIdx.x;
    int rg = tid / 10;            // 0..15
    int cg = tid % 10;            // 0..9
    int row0 = blockIdx.x * 64;
    for (int idx = tid; idx < 64 * 16; idx += 160) {
        int r = idx >> 4, c4 = idx & 15;
        float4 v = make_float4(0.f, 0.f, 0.f, 0.f);
        int gr = row0 + r;
        if (gr < n) v = *(const float4*)&h[(size_t)gr * HID + c4 * 4];
        hs[r][c4 * 4 + 0] = v.x; hs[r][c4 * 4 + 1] = v.y;
        hs[r][c4 * 4 + 2] = v.z; hs[r][c4 * 4 + 3] = v.w;
    }
    for (int i = tid; i < HID * NCLS; i += 160) ws[i] = Wl[i];
    if (tid < NCLS) bs[tid] = bl[tid];
    __syncthreads();
    float acc[4][4];
#pragma unroll
    for (int r = 0; r < 4; r++)
#pragma unroll
        for (int c = 0; c < 4; c++) acc[r][c] = bs[cg * 4 + c];
#pragma unroll 8
    for (int k = 0; k < HID; k++) {
        float xv[4];
#pragma unroll
        for (int r = 0; r < 4; r++) xv[r] = hs[rg * 4 + r][k];
        float4 w = *(float4*)&ws[k * NCLS + cg * 4];
#pragma unroll
        for (int r = 0; r < 4; r++) {
            acc[r][0] += xv[r] * w.x; acc[r][1] += xv[r] * w.y;
            acc[r][2] += xv[r] * w.z; acc[r][3] += xv[r] * w.w;
        }
    }
#pragma unroll
    for (int r = 0; r < 4; r++) {
        int gr = row0 + rg * 4 + r;
        if (gr < n)
            *(float4*)&out[(size_t)gr * NCLS + cg * 4] =
                make_float4(acc[r][0], acc[r][1], acc[r][2], acc[r][3]);
    }
}

// ---------------- launcher --------------------------------------------------
extern "C" void kernel_launch(void* const* d_in, const int* in_sizes, int n_in,
                              void* d_out, int out_size) {
    const float* x    = (const float*)d_in[0];
    const void*  ei   = d_in[1];
    const float* W0   = (const float*)d_in[2];
    const float* a_s0 = (const float*)d_in[3];
    const float* a_d0 = (const float*)d_in[4];
    const float* b0   = (const float*)d_in[5];
    const float* W1   = (const float*)d_in[6];
    const float* a_s1 = (const float*)d_in[7];
    const float* a_d1 = (const float*)d_in[8];
    const float* b1   = (const float*)d_in[9];
    const float* Wl   = (const float*)d_in[10];
    const float* bl   = (const float*)d_in[11];
    float* out = (float*)d_out;

    int n  = in_sizes[0] / IN_DIM;   // 100000
    int E  = in_sizes[1] / 2;        // 1600000
    int ET = E + n;

    __half* hbuf;  cudaGetSymbolAddress((void**)&hbuf, g_h);
    float*  abuf;  cudaGetSymbolAddress((void**)&abuf, g_acc);

    int scanBlocks = (n + SCAN_CHUNK - 1) / SCAN_CHUNK;   // 98
    int edgeBlocks = (ET + 255) / 256;
    int nodeBlocks = (n + 255) / 256;
    int aggBlocks  = ((size_t)n * 8 + 255) / 256;

    // Side stream + events (host objects, created once; no device memory).
    static cudaStream_t s2 = nullptr;
    static cudaEvent_t  evFork = nullptr, evJoin = nullptr;
    if (!s2) {
        cudaStreamCreateWithFlags(&s2, cudaStreamNonBlocking);
        cudaEventCreateWithFlags(&evFork, cudaEventDisableTiming);
        cudaEventCreateWithFlags(&evJoin, cudaEventDisableTiming);
    }
    cudaStream_t ms = 0;   // main (capture) stream

    // ---- fork: CSR build on s2, concurrent with GEMM0 on main stream ----
    cudaEventRecord(evFork, ms);
    cudaStreamWaitEvent(s2, evFork, 0);

    zero_detect_kernel<<<nodeBlocks, 256, 0, s2>>>(ei, n);
    hist_kernel<<<edgeBlocks, 256, 0, s2>>>(ei, E, ET);
    scan1_kernel<<<scanBlocks, SCAN_CHUNK, 0, s2>>>(n);
    scan3_kernel<<<scanBlocks, SCAN_CHUNK, 0, s2>>>(n);
    fill_kernel<<<edgeBlocks, 256, 0, s2>>>(ET);
    cudaEventRecord(evJoin, s2);

    gemm64_kernel<IN_DIM><<<(n + 63) / 64, 256, 0, ms>>>(x, W0, a_s0, a_d0, hbuf, n);

    // ---- join: agg needs both CSR and GEMM0 ----
    cudaStreamWaitEvent(ms, evJoin, 0);
    agg_kernel<<<aggBlocks, 256, 0, ms>>>(hbuf, b0, abuf, n);

    // ---- layer 1 ----
    gemm64_kernel<HID><<<(n + 63) / 64, 256, 0, ms>>>(abuf, W1, a_s1, a_d1, hbuf, n);
    agg_kernel<<<aggBlocks, 256, 0, ms>>>(hbuf, b1, abuf, n);

    // ---- head ----
    logits_kernel<<<(n + 63) / 64, 160, 0, ms>>>(abuf, Wl, bl, out, n);
}